// round 1
// baseline (speedup 1.0000x reference)
#include <cuda_runtime.h>
#include <cuda_bf16.h>
#include <cstdint>

// Problem constants
#define NROWS   200000
#define HSZ     256
#define XSZ     256
#define NARY    4
#define KTOT    1280          // 256 (x) + 1024 (h_cat)
#define CTOT    768           // u(256) | o(256) | h_inner(256)

// GEMM tiling
#define BM 128
#define BN 128
#define BK 16
#define LDA 136               // BK x LDA smem rows, stride%32==8 -> conflict-free frags
#define LDB 136

// Scratch (static device globals: allocation-free rule)
__device__ float g_Bp[KTOT * CTOT];                 // packed tf32 weights, [k][c] row-major
__device__ float g_tmp[(size_t)NROWS * CTOT];       // raw GEMM output [N][768]

__device__ __forceinline__ float to_tf32(float x) {
    uint32_t u;
    asm("cvt.rna.tf32.f32 %0, %1;" : "=r"(u) : "f"(x));
    return __uint_as_float(u);
}

__device__ __forceinline__ void mma_tf32(float d[4], const uint32_t a[4], const uint32_t b[2]) {
    asm volatile(
        "mma.sync.aligned.m16n8k8.row.col.f32.tf32.tf32.f32 "
        "{%0,%1,%2,%3}, {%4,%5,%6,%7}, {%8,%9}, {%0,%1,%2,%3};"
        : "+f"(d[0]), "+f"(d[1]), "+f"(d[2]), "+f"(d[3])
        : "r"(a[0]), "r"(a[1]), "r"(a[2]), "r"(a[3]), "r"(b[0]), "r"(b[1]));
}

// ---------------------------------------------------------------------------
// Kernel 1: pack weights into Bp[k][c], tf32-rounded.
//   c in [0,512): rows 256+c of W_ruo (k<256) / U_ruo (k>=256)  -> u,o gates
//   c in [512,768): zero (k<256) / U_u2 row c-512 (k>=256)      -> h_inner
// ---------------------------------------------------------------------------
__global__ void pack_b_kernel(const float* __restrict__ W_ruo,
                              const float* __restrict__ U_ruo,
                              const float* __restrict__ U_u2) {
    int idx = blockIdx.x * 256 + threadIdx.x;
    if (idx >= KTOT * CTOT) return;
    int k = idx / CTOT;
    int c = idx % CTOT;
    float v;
    if (k < 256) {
        v = (c < 512) ? W_ruo[(256 + c) * XSZ + k] : 0.0f;
    } else {
        int kk = k - 256;
        v = (c < 512) ? U_ruo[(256 + c) * (NARY * HSZ) + kk]
                      : U_u2[(c - 512) * (NARY * HSZ) + kk];
    }
    g_Bp[idx] = to_tf32(v);
}

// ---------------------------------------------------------------------------
// Kernel 2: fused gather + GEMM.  tmp[N,768] = [x | h_cat] @ Bp
// grid = (6 col tiles, 1563 row tiles), 256 threads (8 warps, 4x2 warp grid)
// Col tiles 4,5 (h_inner) skip the x-part of K (weights are zero there).
// ---------------------------------------------------------------------------
__global__ __launch_bounds__(256)
void gemm_kernel(const float* __restrict__ x,
                 const float* __restrict__ h_prev,
                 const int*   __restrict__ child_idx,
                 const int*   __restrict__ child_mask) {
    __shared__ float As[2][BK][LDA];
    __shared__ float Bs[2][BK][LDB];

    const int tid  = threadIdx.x;
    const int warp = tid >> 5;
    const int lane = tid & 31;
    const int wm   = warp >> 1;     // 0..3 -> 32 rows each
    const int wn   = warp & 1;      // 0..1 -> 64 cols each
    const int g    = lane >> 2;     // groupID 0..7
    const int t4   = lane & 3;      // threadID_in_group

    const int rowBase = blockIdx.y * BM;
    const int c0      = blockIdx.x * BN;
    const int kStart  = (blockIdx.x >= 4) ? 256 : 0;
    const int nTiles  = (KTOT - kStart) >> 4;

    // --- A load mapping: each thread owns one row, 8 consecutive k (2 float4)
    const int aRow = tid >> 1;               // 0..127
    const int aK   = (tid & 1) * 8;          // 0 or 8
    const int nRow = rowBase + aRow;
    const bool rowValid = (nRow < NROWS);

    int   cidx[NARY];
    float cmask[NARY];
#pragma unroll
    for (int j = 0; j < NARY; j++) {
        if (rowValid) {
            cidx[j]  = child_idx[nRow * NARY + j];
            cmask[j] = (float)child_mask[nRow * NARY + j];
        } else { cidx[j] = 0; cmask[j] = 0.0f; }
    }

    // --- B load mapping: thread -> (k row, two float4 of cols)
    const int bK = tid >> 4;                 // 0..15
    const int bC = (tid & 15) * 4;           // 0..60

    float4 aReg[2], bReg[2];
    const float4 z4 = make_float4(0.f, 0.f, 0.f, 0.f);

    float acc[2][8][4];
#pragma unroll
    for (int mt = 0; mt < 2; mt++)
#pragma unroll
        for (int nt = 0; nt < 8; nt++)
#pragma unroll
            for (int i = 0; i < 4; i++) acc[mt][nt][i] = 0.0f;

    auto loadTile = [&](int k0) {
        // A (gathered)
        if (k0 < 256) {
            if (rowValid) {
                const float4* p = (const float4*)(x + (size_t)nRow * XSZ + k0 + aK);
                aReg[0] = p[0]; aReg[1] = p[1];
            } else { aReg[0] = z4; aReg[1] = z4; }
        } else {
            const int seg = (k0 - 256) >> 8;
            const int kk  = (k0 - 256) & 255;
            if (cmask[seg] != 0.0f) {
                const float4* p = (const float4*)(h_prev + (size_t)cidx[seg] * HSZ + kk + aK);
                aReg[0] = p[0]; aReg[1] = p[1];
            } else { aReg[0] = z4; aReg[1] = z4; }
        }
        // B (packed weights)
        const float* bp = g_Bp + (size_t)(k0 + bK) * CTOT + c0 + bC;
        bReg[0] = *(const float4*)bp;
        bReg[1] = *(const float4*)(bp + 64);
    };

    auto storeTile = [&](int buf) {
        // A: tf32-round, store transposed [k][m]
#pragma unroll
        for (int q = 0; q < 2; q++) {
            float v[4] = { (&aReg[q].x)[0], (&aReg[q].x)[1], (&aReg[q].x)[2], (&aReg[q].x)[3] };
#pragma unroll
            for (int i = 0; i < 4; i++)
                As[buf][aK + q * 4 + i][aRow] = to_tf32(v[i]);
        }
        // B: already tf32
        *(float4*)&Bs[buf][bK][bC]      = bReg[0];
        *(float4*)&Bs[buf][bK][bC + 64] = bReg[1];
    };

    auto compute = [&](int buf) {
#pragma unroll
        for (int s = 0; s < 2; s++) {
            const int k8 = s * 8;
            uint32_t a[2][4], b[8][2];
#pragma unroll
            for (int mt = 0; mt < 2; mt++) {
                const int m = wm * 32 + mt * 16;
                a[mt][0] = __float_as_uint(As[buf][k8 + t4    ][m + g    ]);
                a[mt][1] = __float_as_uint(As[buf][k8 + t4    ][m + g + 8]);
                a[mt][2] = __float_as_uint(As[buf][k8 + t4 + 4][m + g    ]);
                a[mt][3] = __float_as_uint(As[buf][k8 + t4 + 4][m + g + 8]);
            }
#pragma unroll
            for (int nt = 0; nt < 8; nt++) {
                const int nn = wn * 64 + nt * 8 + g;
                b[nt][0] = __float_as_uint(Bs[buf][k8 + t4    ][nn]);
                b[nt][1] = __float_as_uint(Bs[buf][k8 + t4 + 4][nn]);
            }
#pragma unroll
            for (int mt = 0; mt < 2; mt++)
#pragma unroll
                for (int nt = 0; nt < 8; nt++)
                    mma_tf32(acc[mt][nt], a[mt], b[nt]);
        }
    };

    loadTile(kStart);
    storeTile(0);
    __syncthreads();

    for (int t = 0; t < nTiles; t++) {
        if (t + 1 < nTiles) loadTile(kStart + (t + 1) * BK);
        compute(t & 1);
        if (t + 1 < nTiles) storeTile((t + 1) & 1);
        __syncthreads();
    }

    // Epilogue: write raw accumulators to g_tmp
#pragma unroll
    for (int mt = 0; mt < 2; mt++) {
        const int r0 = rowBase + wm * 32 + mt * 16 + g;
#pragma unroll
        for (int nt = 0; nt < 8; nt++) {
            const int cc = c0 + wn * 64 + nt * 8 + 2 * t4;
            if (r0 < NROWS) {
                float2 v = make_float2(acc[mt][nt][0], acc[mt][nt][1]);
                *(float2*)&g_tmp[(size_t)r0 * CTOT + cc] = v;
            }
            if (r0 + 8 < NROWS) {
                float2 v = make_float2(acc[mt][nt][2], acc[mt][nt][3]);
                *(float2*)&g_tmp[(size_t)(r0 + 8) * CTOT + cc] = v;
            }
        }
    }
}

// ---------------------------------------------------------------------------
// Kernel 3: elementwise GRU epilogue
//   u = sigmoid(tmp[:,0:256] + b[256:512]); o = tanh(tmp[:,256:512] + b[512:768])
//   h = o*u + (1-u)*tmp[:,512:768]
// ---------------------------------------------------------------------------
__global__ void epi_kernel(const float* __restrict__ b_ruo, float* __restrict__ out) {
    int i = blockIdx.x * 256 + threadIdx.x;      // over N*256 (51.2M < 2^31)
    if (i >= NROWS * HSZ) return;
    const int n = i >> 8;
    const int j = i & 255;
    const float* trow = g_tmp + (size_t)n * CTOT;
    float u  = trow[j]        + b_ruo[256 + j];
    float o  = trow[256 + j]  + b_ruo[512 + j];
    float hi = trow[512 + j];
    u = 1.0f / (1.0f + __expf(-u));
    o = tanhf(o);
    out[i] = o * u + (1.0f - u) * hi;
}

// ---------------------------------------------------------------------------
extern "C" void kernel_launch(void* const* d_in, const int* in_sizes, int n_in,
                              void* d_out, int out_size) {
    const float* x          = (const float*)d_in[0];
    const float* h_prev     = (const float*)d_in[1];
    const float* W_ruo      = (const float*)d_in[2];
    const float* U_ruo      = (const float*)d_in[3];
    const float* b_ruo      = (const float*)d_in[4];
    const float* U_u2       = (const float*)d_in[5];
    const int*   child_idx  = (const int*)d_in[6];
    const int*   child_mask = (const int*)d_in[7];
    float*       out        = (float*)d_out;

    pack_b_kernel<<<(KTOT * CTOT + 255) / 256, 256>>>(W_ruo, U_ruo, U_u2);

    dim3 grid(CTOT / BN, (NROWS + BM - 1) / BM);   // (6, 1563)
    gemm_kernel<<<grid, 256>>>(x, h_prev, child_idx, child_mask);

    epi_kernel<<<(NROWS * HSZ + 255) / 256, 256>>>(b_ruo, out);
}

// round 3
// speedup vs baseline: 1.0123x; 1.0123x over previous
#include <cuda_runtime.h>
#include <cstdint>

// Problem constants
#define NROWS   200000
#define KTOT    1280          // 256 (x) + 1024 (h_cat)

// GEMM tiling
#define BM      128
#define BN      192           // 64 u | 64 o | 64 inner columns
#define BK      32
#define NSTAGE  3
#define NT      (KTOT / BK)   // 40

#define LDA     136           // A smem [k][m] row stride (floats)
#define LDB     36            // B smem [n][k] row stride (floats)
#define A_BYTES (BK * LDA * 4)            // 17408
#define B_BYTES (BN * LDB * 4)            // 27648
#define STAGE_BYTES (A_BYTES + B_BYTES)   // 45056
#define SMEM_TOTAL  (NSTAGE * STAGE_BYTES) // 135168
#define LDC     196           // epilogue exchange stride (floats)

// Packed tf32 weights: row c' = b*192 + seg*64 + jj  <->  output col seg*256 + b*64 + jj
__device__ float g_Bp[(size_t)768 * KTOT];

__device__ __forceinline__ float to_tf32(float x) {
    uint32_t u;
    asm("cvt.rna.tf32.f32 %0, %1;" : "=r"(u) : "f"(x));
    return __uint_as_float(u);
}

__device__ __forceinline__ uint32_t smem_u32(const void* p) {
    uint32_t a;
    asm("{ .reg .u64 t; cvta.to.shared.u64 t, %1; cvt.u32.u64 %0, t; }" : "=r"(a) : "l"(p));
    return a;
}

__device__ __forceinline__ void cp_async16(uint32_t dst, const void* src) {
    asm volatile("cp.async.ca.shared.global [%0], [%1], 16;" :: "r"(dst), "l"(src) : "memory");
}
#define CP_COMMIT()  asm volatile("cp.async.commit_group;" ::: "memory")
#define CP_WAIT1()   asm volatile("cp.async.wait_group 1;" ::: "memory")

__device__ __forceinline__ void mma_tf32(float d[4], const uint32_t a[4], const uint32_t b[2]) {
    asm volatile(
        "mma.sync.aligned.m16n8k8.row.col.f32.tf32.tf32.f32 "
        "{%0,%1,%2,%3}, {%4,%5,%6,%7}, {%8,%9}, {%0,%1,%2,%3};"
        : "+f"(d[0]), "+f"(d[1]), "+f"(d[2]), "+f"(d[3])
        : "r"(a[0]), "r"(a[1]), "r"(a[2]), "r"(a[3]), "r"(b[0]), "r"(b[1]));
}

// ---------------------------------------------------------------------------
// Kernel 1: pack weights, tf32-rounded, block-friendly row order.
//   c' = b*192 + seg*64 + jj ; output col = seg*256 + b*64 + jj
//   seg 0: u = W_ruo row 256+col (k<256) | U_ruo row 256+col (k>=256)
//   seg 1: o = W_ruo row 512+col        | U_ruo row 512+col
//   seg 2: inner = 0 (k<256)            | U_u2 row col
// ---------------------------------------------------------------------------
__global__ void pack_b_kernel(const float* __restrict__ W_ruo,
                              const float* __restrict__ U_ruo,
                              const float* __restrict__ U_u2) {
    int idx = blockIdx.x * 256 + threadIdx.x;
    if (idx >= 768 * KTOT) return;
    int cp = idx / KTOT;
    int k  = idx % KTOT;
    int b   = cp / 192;
    int r   = cp % 192;
    int seg = r / 64;
    int jj  = r % 64;
    int col = b * 64 + jj;
    float v;
    if (seg < 2) {
        int wrow = 256 + seg * 256 + col;
        v = (k < 256) ? W_ruo[wrow * 256 + k] : U_ruo[wrow * 1024 + (k - 256)];
    } else {
        v = (k < 256) ? 0.0f : U_u2[col * 1024 + (k - 256)];
    }
    g_Bp[idx] = to_tf32(v);
}

// ---------------------------------------------------------------------------
// Kernel 2: fused gather + GEMM + GRU epilogue.
// grid = (4 col blocks of 64 output cols, 1563 row blocks), 256 threads.
// ---------------------------------------------------------------------------
__global__ __launch_bounds__(256, 1)
void gemm_kernel(const float* __restrict__ x,
                 const float* __restrict__ h_prev,
                 const int*   __restrict__ child_idx,
                 const int*   __restrict__ child_mask,
                 const float* __restrict__ b_ruo,
                 float*       __restrict__ out) {
    extern __shared__ float smem[];
    const uint32_t sbase = smem_u32(smem);

    const int tid  = threadIdx.x;
    const int warp = tid >> 5;
    const int lane = tid & 31;
    const int wm   = warp >> 2;       // 0..1 -> 64 rows
    const int wn   = warp & 3;        // 0..3 -> 48 cols
    const int g    = lane >> 2;       // 0..7
    const int t4   = lane & 3;        // 0..3

    const int rowBase = blockIdx.y * BM;
    const int c0      = blockIdx.x * BN;   // g_Bp row base

    // --- A gather state: thread owns row (tid&127), k-half (tid>>7)*16 ---
    const int  aRow = tid & 127;
    const int  kh   = (tid >> 7) * 16;
    const int  nRow = rowBase + aRow;
    const bool rv   = (nRow < NROWS);
    const int  srcRow = rv ? nRow : 0;
    int  cidx[4];
    bool cok[4];
#pragma unroll
    for (int j = 0; j < 4; j++) {
        if (rv) {
            cidx[j] = child_idx[nRow * 4 + j];
            cok[j]  = (child_mask[nRow * 4 + j] != 0);
        } else { cidx[j] = 0; cok[j] = false; }
    }

    float acc[4][6][4];
#pragma unroll
    for (int mt = 0; mt < 4; mt++)
#pragma unroll
        for (int nt = 0; nt < 6; nt++)
#pragma unroll
            for (int i = 0; i < 4; i++) acc[mt][nt][i] = 0.0f;

    float4 av[4];
    const float4 z4 = make_float4(0.f, 0.f, 0.f, 0.f);

    // Issue this thread's 16-float A load for k-tile at k0 (gathered)
    auto loadA = [&](int k0) {
        const int k = k0 + kh;
        if (k < 256) {
            const float4* p = (const float4*)(x + (size_t)srcRow * 256 + k);
#pragma unroll
            for (int j = 0; j < 4; j++) av[j] = p[j];
        } else {
            const int seg = (k - 256) >> 8;
            const int kk  = (k - 256) & 255;
            if (cok[seg]) {
                const float4* p = (const float4*)(h_prev + (size_t)cidx[seg] * 256 + kk);
#pragma unroll
                for (int j = 0; j < 4; j++) av[j] = p[j];
            } else {
#pragma unroll
                for (int j = 0; j < 4; j++) av[j] = z4;
            }
        }
    };

    // Round + store A transposed into stage s: As[k][m]
    auto storeA = [&](int s) {
        float* As = smem + s * (STAGE_BYTES / 4);
#pragma unroll
        for (int j = 0; j < 4; j++) {
            float v[4] = { av[j].x, av[j].y, av[j].z, av[j].w };
#pragma unroll
            for (int c = 0; c < 4; c++)
                As[(kh + j * 4 + c) * LDA + aRow] = to_tf32(v[c]);
        }
    };

    // cp.async B tile into stage s (192 rows x 32 k)
    auto loadB = [&](int s, int k0) {
        const uint32_t bb = sbase + s * STAGE_BYTES + A_BYTES;
#pragma unroll
        for (int j = 0; j < 6; j++) {
            const int c    = tid + 256 * j;
            const int rowb = c >> 3;
            const int ch   = c & 7;
            cp_async16(bb + rowb * (LDB * 4) + ch * 16,
                       g_Bp + (size_t)(c0 + rowb) * KTOT + k0 + ch * 4);
        }
    };

    auto compute = [&](int s) {
        const float* As = smem + s * (STAGE_BYTES / 4);
        const float* Bs = As + BK * LDA;
#pragma unroll
        for (int ks = 0; ks < 4; ks++) {
            const int k8 = ks * 8;
            uint32_t a[4][4], b[6][2];
#pragma unroll
            for (int mt = 0; mt < 4; mt++) {
                const int m = wm * 64 + mt * 16 + g;
                a[mt][0] = __float_as_uint(As[(k8 + t4) * LDA + m]);
                a[mt][1] = __float_as_uint(As[(k8 + t4) * LDA + m + 8]);
                a[mt][2] = __float_as_uint(As[(k8 + t4 + 4) * LDA + m]);
                a[mt][3] = __float_as_uint(As[(k8 + t4 + 4) * LDA + m + 8]);
            }
#pragma unroll
            for (int nt = 0; nt < 6; nt++) {
                const int n = wn * 48 + nt * 8 + g;
                b[nt][0] = __float_as_uint(Bs[n * LDB + k8 + t4]);
                b[nt][1] = __float_as_uint(Bs[n * LDB + k8 + t4 + 4]);
            }
#pragma unroll
            for (int mt = 0; mt < 4; mt++)
#pragma unroll
                for (int nt = 0; nt < 6; nt++)
                    mma_tf32(acc[mt][nt], a[mt], b[nt]);
        }
    };

    // --- Prologue: stages 0,1 ---
#pragma unroll
    for (int s = 0; s < NSTAGE - 1; s++) {
        loadA(s * BK);
        storeA(s);
        loadB(s, s * BK);
        CP_COMMIT();
    }

    // --- Main pipeline ---
    for (int t = 0; t < NT; t++) {
        CP_WAIT1();
        __syncthreads();
        const int  tl = t + NSTAGE - 1;
        const bool dl = (tl < NT);
        if (dl) loadA(tl * BK);            // issue LDGs early; consumed after compute
        compute(t % NSTAGE);
        if (dl) {
            storeA(tl % NSTAGE);
            loadB(tl % NSTAGE, tl * BK);
        }
        CP_COMMIT();                       // empty group when !dl keeps wait_group accounting
    }

    // --- Epilogue: exchange through smem, fuse GRU math, write out ---
    __syncthreads();
    float* Cs = smem;                      // reuse stage buffers (needs 128*196*4 = 100352 B)
#pragma unroll
    for (int mt = 0; mt < 4; mt++) {
        const int r = wm * 64 + mt * 16 + g;
#pragma unroll
        for (int nt = 0; nt < 6; nt++) {
            const int c = wn * 48 + nt * 8 + 2 * t4;
            *(float2*)&Cs[r * LDC + c]       = make_float2(acc[mt][nt][0], acc[mt][nt][1]);
            *(float2*)&Cs[(r + 8) * LDC + c] = make_float2(acc[mt][nt][2], acc[mt][nt][3]);
        }
    }
    __syncthreads();

    const int bcol = blockIdx.x * 64;
#pragma unroll
    for (int it = 0; it < 8; it++) {
        const int lin = it * 256 + tid;    // 0..2047 over 128 rows x 16 quads
        const int row = lin >> 4;
        const int jj  = (lin & 15) * 4;
        const int n   = rowBase + row;
        float4 u4 = *(const float4*)&Cs[row * LDC + jj];
        float4 o4 = *(const float4*)&Cs[row * LDC + 64 + jj];
        float4 i4 = *(const float4*)&Cs[row * LDC + 128 + jj];
        float4 bu = *(const float4*)(b_ruo + 256 + bcol + jj);
        float4 bo = *(const float4*)(b_ruo + 512 + bcol + jj);
        float4 res;
#pragma unroll
        for (int c = 0; c < 4; c++) {
            float u = (&u4.x)[c] + (&bu.x)[c];
            float o = (&o4.x)[c] + (&bo.x)[c];
            float h = (&i4.x)[c];
            u = 1.0f / (1.0f + __expf(-u));
            o = tanhf(o);
            (&res.x)[c] = o * u + (1.0f - u) * h;
        }
        if (n < NROWS)
            *(float4*)(out + (size_t)n * 256 + bcol + jj) = res;
    }
}

// ---------------------------------------------------------------------------
extern "C" void kernel_launch(void* const* d_in, const int* in_sizes, int n_in,
                              void* d_out, int out_size) {
    const float* x          = (const float*)d_in[0];
    const float* h_prev     = (const float*)d_in[1];
    const float* W_ruo      = (const float*)d_in[2];
    const float* U_ruo      = (const float*)d_in[3];
    const float* b_ruo      = (const float*)d_in[4];
    const float* U_u2       = (const float*)d_in[5];
    const int*   child_idx  = (const int*)d_in[6];
    const int*   child_mask = (const int*)d_in[7];
    float*       out        = (float*)d_out;

    cudaFuncSetAttribute(gemm_kernel, cudaFuncAttributeMaxDynamicSharedMemorySize, SMEM_TOTAL);

    pack_b_kernel<<<(768 * KTOT + 255) / 256, 256>>>(W_ruo, U_ruo, U_u2);

    dim3 grid(4, (NROWS + BM - 1) / BM);   // (4, 1563)
    gemm_kernel<<<grid, 256, SMEM_TOTAL>>>(x, h_prev, child_idx, child_mask, b_ruo, out);
}